// round 3
// baseline (speedup 1.0000x reference)
#include <cuda_runtime.h>

// SNN forward: 3 layers of (GEMM + Leaky LIF), T=100 steps, B=128, fp32 I/O.
//
// Round 3: numerics strategy =
//   L0/L1: fp32 GEMM mimicking cuBLAS splitK=4 summation order
//          (4 contiguous K-chunks of 512, sequential ascending FFMA within
//           chunk, partials combined in ascending chunk order) -> aiming for
//          bit-exact match with the reference's GPU GEMM.
//   L2:    fp64-exact accumulation (safe fallback; small element count keeps
//          expected spike flips ~0-1).
//
// out layout (row-major [T,B,d] each, concatenated):
//   spk0 [100,128,2048] | spk1 [100,128,2048] | spk2 [100,128,512]
//   mem0 [100,128,2048] | mem1 [100,128,2048] | mem2 [100,128,512]

#define T_STEPS 100
#define BATCH   128

// ---------------------------------------------------------------------------
// fp32 GEMM + LIF, splitK-mimic accumulation.
// Tile: BM=128 (full batch), BN=16, BK=32. 256 threads, 4x2 microtile.
// CHUNK_TILES = 16 -> chunk width 512 (splitK=4 over K=2048).
// ---------------------------------------------------------------------------
__global__ void __launch_bounds__(256, 2) gemm_lif_f32_split(
    const float* __restrict__ A, long lda,
    const float* __restrict__ W, int K, int H,
    const float* __restrict__ th_ptr,
    const float* __restrict__ mem_prev,   // nullptr at t==0
    float* __restrict__ mem_out,
    float* __restrict__ spk_out)
{
    const int BK = 32, BN = 16;
    const int CHUNK_TILES = 16;                 // 16*32 = 512 k per chunk
    __shared__ __align__(16) float As[BK][132];
    __shared__ __align__(16) float Ws[BK][18];

    const int tid = threadIdx.x;
    const int j0  = blockIdx.x * BN;

    const int tx = tid & 7;    // cols tx*2 .. tx*2+1
    const int ty = tid >> 3;   // rows ty*4 .. ty*4+3

    const int arow = tid >> 3;          // 0..31
    const int akv  = (tid & 7) * 4;
    const int wrow = tid >> 4;          // 0..15
    const int wkv  = (tid & 15) * 2;

    float acc[4][2];   // current chunk accumulator (sequential-k within chunk)
    float res[4][2];   // combined result across chunks (ascending order)
#pragma unroll
    for (int i = 0; i < 4; i++) {
        acc[i][0] = 0.f; acc[i][1] = 0.f;
        res[i][0] = 0.f; res[i][1] = 0.f;
    }

    const int ntiles = K / BK;

    float4 aReg[4];
    float2 wReg;

    // prefetch tile 0
    {
        const float* Ak = A + akv;
#pragma unroll
        for (int r = 0; r < 4; r++)
            aReg[r] = *reinterpret_cast<const float4*>(Ak + (long)(arow + 32 * r) * lda);
        wReg = *reinterpret_cast<const float2*>(W + (long)(j0 + wrow) * K + wkv);
    }

    for (int tile = 0; tile < ntiles; tile++) {
        // commit prefetched tile to smem (transposed)
#pragma unroll
        for (int r = 0; r < 4; r++) {
            As[akv + 0][arow + 32 * r] = aReg[r].x;
            As[akv + 1][arow + 32 * r] = aReg[r].y;
            As[akv + 2][arow + 32 * r] = aReg[r].z;
            As[akv + 3][arow + 32 * r] = aReg[r].w;
        }
        Ws[wkv + 0][wrow] = wReg.x;
        Ws[wkv + 1][wrow] = wReg.y;
        __syncthreads();

        // prefetch next tile while computing this one
        if (tile + 1 < ntiles) {
            const float* Ak = A + (long)(tile + 1) * BK + akv;
#pragma unroll
            for (int r = 0; r < 4; r++)
                aReg[r] = *reinterpret_cast<const float4*>(Ak + (long)(arow + 32 * r) * lda);
            wReg = *reinterpret_cast<const float2*>(
                W + (long)(j0 + wrow) * K + (long)(tile + 1) * BK + wkv);
        }

        // sequential ascending-k FFMA chain (within the current chunk)
#pragma unroll
        for (int kk = 0; kk < BK; kk++) {
            float4 ra = *reinterpret_cast<const float4*>(&As[kk][ty * 4]);
            float2 rb = *reinterpret_cast<const float2*>(&Ws[kk][tx * 2]);
            acc[0][0] = fmaf(ra.x, rb.x, acc[0][0]);  acc[0][1] = fmaf(ra.x, rb.y, acc[0][1]);
            acc[1][0] = fmaf(ra.y, rb.x, acc[1][0]);  acc[1][1] = fmaf(ra.y, rb.y, acc[1][1]);
            acc[2][0] = fmaf(ra.z, rb.x, acc[2][0]);  acc[2][1] = fmaf(ra.z, rb.y, acc[2][1]);
            acc[3][0] = fmaf(ra.w, rb.x, acc[3][0]);  acc[3][1] = fmaf(ra.w, rb.y, acc[3][1]);
        }
        __syncthreads();

        // chunk boundary: fold partial into result (ascending chunk order)
        if ((tile & (CHUNK_TILES - 1)) == (CHUNK_TILES - 1)) {
#pragma unroll
            for (int i = 0; i < 4; i++) {
                res[i][0] += acc[i][0];  acc[i][0] = 0.f;
                res[i][1] += acc[i][1];  acc[i][1] = 0.f;
            }
        }
    }

    // fused LIF epilogue (fp32, mirrors reference elementwise rounding:
    // 0.5*m exact, reset*th exact, two roundings total)
    const float th = *th_ptr;
#pragma unroll
    for (int i = 0; i < 4; i++) {
        const int b = ty * 4 + i;
#pragma unroll
        for (int jj = 0; jj < 2; jj++) {
            const int col = j0 + tx * 2 + jj;
            const long idx = (long)b * H + col;
            float cur   = res[i][jj];
            float mprev = mem_prev ? mem_prev[idx] : 0.f;
            float reset = (mprev - th > 0.f) ? 1.f : 0.f;
            float mem   = 0.5f * mprev + cur;
            mem -= reset * th;
            float spk = (mem - th > 0.f) ? 1.f : 0.f;
            mem_out[idx] = mem;
            spk_out[idx] = spk;
        }
    }
}

// ---------------------------------------------------------------------------
// fp64-exact GEMM + LIF (layer 2). BM=128, BN=8, BK=32, 256 threads, 2x2.
// ---------------------------------------------------------------------------
__global__ void __launch_bounds__(256) gemm_lif_f64(
    const float* __restrict__ A, long lda,
    const float* __restrict__ W, int K, int H,
    const float* __restrict__ th_ptr,
    const float* __restrict__ mem_prev,
    float* __restrict__ mem_out,
    float* __restrict__ spk_out)
{
    constexpr int BK = 32, BN = 8, TM = 2;
    constexpr int TXG = BN / 2;          // 4 col groups
    __shared__ __align__(16) double As[BK][130];
    __shared__ __align__(16) double Ws[BK][BN + 2];

    const int tid = threadIdx.x;
    const int j0  = blockIdx.x * BN;

    const int tx = tid % TXG;
    const int ty = tid / TXG;

    const int arow = tid >> 3;
    const int akv  = (tid & 7) * 4;
    const int wrow = tid >> 5;           // 0..7
    const int wkv  = (tid & 31);         // 0..31

    double acc[TM][2];
#pragma unroll
    for (int i = 0; i < TM; i++) { acc[i][0] = 0.0; acc[i][1] = 0.0; }

    const int ntiles = K / BK;

    float4 aReg[4];
    float  wReg;

    {
        const float* Ak = A + akv;
#pragma unroll
        for (int r = 0; r < 4; r++)
            aReg[r] = *reinterpret_cast<const float4*>(Ak + (long)(arow + 32 * r) * lda);
        wReg = W[(long)(j0 + wrow) * K + wkv];
    }

    for (int tile = 0; tile < ntiles; tile++) {
#pragma unroll
        for (int r = 0; r < 4; r++) {
            As[akv + 0][arow + 32 * r] = (double)aReg[r].x;
            As[akv + 1][arow + 32 * r] = (double)aReg[r].y;
            As[akv + 2][arow + 32 * r] = (double)aReg[r].z;
            As[akv + 3][arow + 32 * r] = (double)aReg[r].w;
        }
        Ws[wkv][wrow] = (double)wReg;
        __syncthreads();

        if (tile + 1 < ntiles) {
            const float* Ak = A + (long)(tile + 1) * BK + akv;
#pragma unroll
            for (int r = 0; r < 4; r++)
                aReg[r] = *reinterpret_cast<const float4*>(Ak + (long)(arow + 32 * r) * lda);
            wReg = W[(long)(j0 + wrow) * K + (long)(tile + 1) * BK + wkv];
        }

#pragma unroll
        for (int kk = 0; kk < BK; kk++) {
            double2 rb = *reinterpret_cast<const double2*>(&Ws[kk][tx * 2]);
            double2 r2 = *reinterpret_cast<const double2*>(&As[kk][ty * TM]);
            acc[0][0] = fma(r2.x, rb.x, acc[0][0]);
            acc[0][1] = fma(r2.x, rb.y, acc[0][1]);
            acc[1][0] = fma(r2.y, rb.x, acc[1][0]);
            acc[1][1] = fma(r2.y, rb.y, acc[1][1]);
        }
        __syncthreads();
    }

    const float th = *th_ptr;
#pragma unroll
    for (int i = 0; i < TM; i++) {
        const int b = ty * TM + i;
#pragma unroll
        for (int jj = 0; jj < 2; jj++) {
            const int col = j0 + tx * 2 + jj;
            const long idx = (long)b * H + col;
            float cur   = (float)acc[i][jj];
            float mprev = mem_prev ? mem_prev[idx] : 0.f;
            float reset = (mprev - th > 0.f) ? 1.f : 0.f;
            float mem   = 0.5f * mprev + cur;
            mem -= reset * th;
            float spk = (mem - th > 0.f) ? 1.f : 0.f;
            mem_out[idx] = mem;
            spk_out[idx] = spk;
        }
    }
}

extern "C" void kernel_launch(void* const* d_in, const int* in_sizes, int n_in,
                              void* d_out, int out_size)
{
    const float* x   = (const float*)d_in[0];  // [B=128, T=100, 2048]
    const float* W0  = (const float*)d_in[1];  // [2048, 2048]
    const float* W1  = (const float*)d_in[2];  // [2048, 2048]
    const float* W2  = (const float*)d_in[3];  // [512, 2048]
    const float* th0 = (const float*)d_in[4];
    const float* th1 = (const float*)d_in[5];
    const float* th2 = (const float*)d_in[6];

    float* out = (float*)d_out;

    const long S0 = (long)T_STEPS * BATCH * 2048;
    const long S2 = (long)T_STEPS * BATCH * 512;

    float* spk0 = out;
    float* spk1 = out + S0;
    float* spk2 = out + 2 * S0;
    float* mem0 = out + 2 * S0 + S2;
    float* mem1 = mem0 + S0;
    float* mem2 = mem1 + S0;

    const long ldx = (long)T_STEPS * 2048;

    for (int t = 0; t < T_STEPS; t++) {
        const long o0 = (long)t * BATCH * 2048;
        const long o2 = (long)t * BATCH * 512;

        // Layer 0: A = x[:, t, :] (strided rows), K=2048, H=2048
        gemm_lif_f32_split<<<2048 / 16, 256>>>(
            x + (long)t * 2048, ldx, W0, 2048, 2048, th0,
            t ? (mem0 + o0 - (long)BATCH * 2048) : nullptr,
            mem0 + o0, spk0 + o0);

        // Layer 1: A = spk0[t] (contiguous), K=2048, H=2048
        gemm_lif_f32_split<<<2048 / 16, 256>>>(
            spk0 + o0, 2048L, W1, 2048, 2048, th1,
            t ? (mem1 + o0 - (long)BATCH * 2048) : nullptr,
            mem1 + o0, spk1 + o0);

        // Layer 2: A = spk1[t], K=2048, H=512 (fp64-exact)
        gemm_lif_f64<<<512 / 8, 256>>>(
            spk1 + o0, 2048L, W2, 2048, 512, th2,
            t ? (mem2 + o2 - (long)BATCH * 512) : nullptr,
            mem2 + o2, spk2 + o2);
    }
}

// round 4
// speedup vs baseline: 1.9782x; 1.9782x over previous
#include <cuda_runtime.h>

// SNN forward: 3 layers of (GEMM + Leaky LIF), T=100 steps, B=128, fp32 I/O.
//
// Numerics contract (validated round 3, rel_err 2.2e-7):
//   L0/L1: fp32, splitK=4 summation order: 4 contiguous K-chunks of 512,
//          sequential ascending FFMA within chunk, partials folded
//          ((p0+p1)+p2)+p3. LIF epilogue: mem = 0.5*mprev + cur; mem -= reset*th.
//   L2:    fp64-exact accumulation (fold in fp64, single round to fp32).
//
// Round 4: chunks go to separate CTAs (partials in __device__ scratch) to fix
// occupancy (grid 128 -> 256), fold+LIF in a cheap elementwise kernel that
// reproduces the exact fold order bit-for-bit.

#define T_STEPS 100
#define BATCH   128

__device__ float  g_part32[4 * BATCH * 2048];   // fp32 chunk partials (L0/L1)
__device__ double g_part64[4 * BATCH * 512];    // fp64 chunk partials (L2)

// ---------------------------------------------------------------------------
// fp32 partial GEMM: part[chunk][b][j] = sum_{k in chunk} A[b,k] * W[j,k]
// BM=128 (full batch), BN=32, BK=16. 256 threads, 4x4 microtile.
// grid = (H/32, 4 chunks). Sequential ascending-k FFMA chain per output.
// ---------------------------------------------------------------------------
__global__ void __launch_bounds__(256) gemm_partial_f32(
    const float* __restrict__ A, long lda,
    const float* __restrict__ W, int K, int H)
{
    __shared__ __align__(16) float As[16][132];
    __shared__ __align__(16) float Ws[16][36];

    const int tid   = threadIdx.x;
    const int j0    = blockIdx.x * 32;
    const int chunk = blockIdx.y;
    const long kbase = (long)chunk * 512;

    const int tx = tid & 7;    // cols j0 + tx*4 .. +3
    const int ty = tid >> 3;   // rows ty*4 .. +3

    const int aro = tid >> 2;        // 0..63 (rows aro, aro+64)
    const int akv = (tid & 3) * 4;   // k offset within 16
    const int wro = tid >> 3;        // 0..31
    const int wkv = (tid & 7) * 2;   // k offset within 16

    float acc[4][4];
#pragma unroll
    for (int i = 0; i < 4; i++)
#pragma unroll
        for (int j = 0; j < 4; j++) acc[i][j] = 0.f;

    const float* Ab = A + kbase;
    const float* Wb = W + kbase;

    float4 aReg[2];
    float2 wReg;

    aReg[0] = *(const float4*)(Ab + (long)aro        * lda + akv);
    aReg[1] = *(const float4*)(Ab + (long)(aro + 64) * lda + akv);
    wReg    = *(const float2*)(Wb + (long)(j0 + wro) * K   + wkv);

    for (int tile = 0; tile < 32; tile++) {
        As[akv + 0][aro]      = aReg[0].x;
        As[akv + 1][aro]      = aReg[0].y;
        As[akv + 2][aro]      = aReg[0].z;
        As[akv + 3][aro]      = aReg[0].w;
        As[akv + 0][aro + 64] = aReg[1].x;
        As[akv + 1][aro + 64] = aReg[1].y;
        As[akv + 2][aro + 64] = aReg[1].z;
        As[akv + 3][aro + 64] = aReg[1].w;
        Ws[wkv + 0][wro] = wReg.x;
        Ws[wkv + 1][wro] = wReg.y;
        __syncthreads();

        if (tile + 1 < 32) {
            const long ko = (long)(tile + 1) * 16;
            aReg[0] = *(const float4*)(Ab + (long)aro        * lda + ko + akv);
            aReg[1] = *(const float4*)(Ab + (long)(aro + 64) * lda + ko + akv);
            wReg    = *(const float2*)(Wb + (long)(j0 + wro) * K   + ko + wkv);
        }

#pragma unroll
        for (int kk = 0; kk < 16; kk++) {
            float4 ra = *(const float4*)&As[kk][ty * 4];
            float4 rb = *(const float4*)&Ws[kk][tx * 4];
            acc[0][0] = fmaf(ra.x, rb.x, acc[0][0]);
            acc[0][1] = fmaf(ra.x, rb.y, acc[0][1]);
            acc[0][2] = fmaf(ra.x, rb.z, acc[0][2]);
            acc[0][3] = fmaf(ra.x, rb.w, acc[0][3]);
            acc[1][0] = fmaf(ra.y, rb.x, acc[1][0]);
            acc[1][1] = fmaf(ra.y, rb.y, acc[1][1]);
            acc[1][2] = fmaf(ra.y, rb.z, acc[1][2]);
            acc[1][3] = fmaf(ra.y, rb.w, acc[1][3]);
            acc[2][0] = fmaf(ra.z, rb.x, acc[2][0]);
            acc[2][1] = fmaf(ra.z, rb.y, acc[2][1]);
            acc[2][2] = fmaf(ra.z, rb.z, acc[2][2]);
            acc[2][3] = fmaf(ra.z, rb.w, acc[2][3]);
            acc[3][0] = fmaf(ra.w, rb.x, acc[3][0]);
            acc[3][1] = fmaf(ra.w, rb.y, acc[3][1]);
            acc[3][2] = fmaf(ra.w, rb.z, acc[3][2]);
            acc[3][3] = fmaf(ra.w, rb.w, acc[3][3]);
        }
        __syncthreads();
    }

    float* dst = g_part32 + (long)chunk * (BATCH * (long)H);
#pragma unroll
    for (int i = 0; i < 4; i++) {
        const int b = ty * 4 + i;
        *(float4*)(dst + (long)b * H + j0 + tx * 4) =
            make_float4(acc[i][0], acc[i][1], acc[i][2], acc[i][3]);
    }
}

// ---------------------------------------------------------------------------
// Fold 4 fp32 partials (ascending order) + LIF. n4 = B*H/4 float4 elements.
// ---------------------------------------------------------------------------
__global__ void __launch_bounds__(256) fold_lif_f32(
    const float* __restrict__ th_ptr,
    const float* __restrict__ mem_prev,   // nullptr at t==0
    float* __restrict__ mem_out,
    float* __restrict__ spk_out,
    int n4)
{
    const int i = blockIdx.x * 256 + threadIdx.x;
    if (i >= n4) return;

    const float4* p = (const float4*)g_part32;
    float4 r0 = p[i];
    float4 r1 = p[i + n4];
    float4 r2 = p[i + 2 * n4];
    float4 r3 = p[i + 3 * n4];
    const float th = *th_ptr;
    float4 mp = mem_prev ? ((const float4*)mem_prev)[i]
                         : make_float4(0.f, 0.f, 0.f, 0.f);

    float4 mem, spk;
#define LIF1(c)                                                   \
    {                                                             \
        float cur   = ((r0.c + r1.c) + r2.c) + r3.c;              \
        float reset = (mp.c - th > 0.f) ? 1.f : 0.f;              \
        float m     = 0.5f * mp.c + cur;                          \
        m -= reset * th;                                          \
        mem.c = m;                                                \
        spk.c = (m - th > 0.f) ? 1.f : 0.f;                       \
    }
    LIF1(x) LIF1(y) LIF1(z) LIF1(w)
#undef LIF1

    ((float4*)mem_out)[i] = mem;
    ((float4*)spk_out)[i] = spk;
}

// ---------------------------------------------------------------------------
// fp64 partial GEMM (layer 2, exact). BM=128, BN=16, BK=16. 256 thr, 4x2.
// grid = (H/16, 4 chunks). A is contiguous (lda = K = 2048).
// ---------------------------------------------------------------------------
__global__ void __launch_bounds__(256) gemm_partial_f64(
    const float* __restrict__ A,
    const float* __restrict__ W, int K, int H)
{
    __shared__ __align__(16) double As[16][130];
    __shared__ __align__(16) double Ws[16][18];

    const int tid   = threadIdx.x;
    const int j0    = blockIdx.x * 16;
    const int chunk = blockIdx.y;
    const long kbase = (long)chunk * 512;

    const int tx = tid & 7;    // cols j0 + tx*2 .. +1
    const int ty = tid >> 3;   // rows ty*4 .. +3

    const int aro = tid >> 2;
    const int akv = (tid & 3) * 4;
    const int wro = tid >> 4;        // 0..15
    const int wk  = tid & 15;        // 0..15

    double acc[4][2];
#pragma unroll
    for (int i = 0; i < 4; i++) { acc[i][0] = 0.0; acc[i][1] = 0.0; }

    const float* Ab = A + kbase;
    const float* Wb = W + kbase;

    float4 aReg[2];
    float  wReg;

    aReg[0] = *(const float4*)(Ab + (long)aro        * K + akv);
    aReg[1] = *(const float4*)(Ab + (long)(aro + 64) * K + akv);
    wReg    = Wb[(long)(j0 + wro) * K + wk];

    for (int tile = 0; tile < 32; tile++) {
        As[akv + 0][aro]      = (double)aReg[0].x;
        As[akv + 1][aro]      = (double)aReg[0].y;
        As[akv + 2][aro]      = (double)aReg[0].z;
        As[akv + 3][aro]      = (double)aReg[0].w;
        As[akv + 0][aro + 64] = (double)aReg[1].x;
        As[akv + 1][aro + 64] = (double)aReg[1].y;
        As[akv + 2][aro + 64] = (double)aReg[1].z;
        As[akv + 3][aro + 64] = (double)aReg[1].w;
        Ws[wk][wro] = (double)wReg;
        __syncthreads();

        if (tile + 1 < 32) {
            const long ko = (long)(tile + 1) * 16;
            aReg[0] = *(const float4*)(Ab + (long)aro        * K + ko + akv);
            aReg[1] = *(const float4*)(Ab + (long)(aro + 64) * K + ko + akv);
            wReg    = Wb[(long)(j0 + wro) * K + ko + wk];
        }

#pragma unroll
        for (int kk = 0; kk < 16; kk++) {
            double2 rb = *(const double2*)&Ws[kk][tx * 2];
            double2 a0 = *(const double2*)&As[kk][ty * 4];
            double2 a1 = *(const double2*)&As[kk][ty * 4 + 2];
            acc[0][0] = fma(a0.x, rb.x, acc[0][0]);
            acc[0][1] = fma(a0.x, rb.y, acc[0][1]);
            acc[1][0] = fma(a0.y, rb.x, acc[1][0]);
            acc[1][1] = fma(a0.y, rb.y, acc[1][1]);
            acc[2][0] = fma(a1.x, rb.x, acc[2][0]);
            acc[2][1] = fma(a1.x, rb.y, acc[2][1]);
            acc[3][0] = fma(a1.y, rb.x, acc[3][0]);
            acc[3][1] = fma(a1.y, rb.y, acc[3][1]);
        }
        __syncthreads();
    }

    double* dst = g_part64 + (long)chunk * (BATCH * (long)H);
#pragma unroll
    for (int i = 0; i < 4; i++) {
        const int b = ty * 4 + i;
        *(double2*)(dst + (long)b * H + j0 + tx * 2) =
            make_double2(acc[i][0], acc[i][1]);
    }
}

// ---------------------------------------------------------------------------
// Fold 4 fp64 partials + LIF (layer 2). n = B*H scalars.
// ---------------------------------------------------------------------------
__global__ void __launch_bounds__(256) fold_lif_f64(
    const float* __restrict__ th_ptr,
    const float* __restrict__ mem_prev,
    float* __restrict__ mem_out,
    float* __restrict__ spk_out,
    int n)
{
    const int i = blockIdx.x * 256 + threadIdx.x;
    if (i >= n) return;

    double r = ((g_part64[i] + g_part64[i + n]) + g_part64[i + 2 * n])
               + g_part64[i + 3 * n];
    const float th = *th_ptr;
    float cur   = (float)r;
    float mp    = mem_prev ? mem_prev[i] : 0.f;
    float reset = (mp - th > 0.f) ? 1.f : 0.f;
    float mem   = 0.5f * mp + cur;
    mem -= reset * th;
    mem_out[i] = mem;
    spk_out[i] = (mem - th > 0.f) ? 1.f : 0.f;
}

extern "C" void kernel_launch(void* const* d_in, const int* in_sizes, int n_in,
                              void* d_out, int out_size)
{
    const float* x   = (const float*)d_in[0];  // [B=128, T=100, 2048]
    const float* W0  = (const float*)d_in[1];  // [2048, 2048]
    const float* W1  = (const float*)d_in[2];  // [2048, 2048]
    const float* W2  = (const float*)d_in[3];  // [512, 2048]
    const float* th0 = (const float*)d_in[4];
    const float* th1 = (const float*)d_in[5];
    const float* th2 = (const float*)d_in[6];

    float* out = (float*)d_out;

    const long S0 = (long)T_STEPS * BATCH * 2048;
    const long S2 = (long)T_STEPS * BATCH * 512;

    float* spk0 = out;
    float* spk1 = out + S0;
    float* spk2 = out + 2 * S0;
    float* mem0 = out + 2 * S0 + S2;
    float* mem1 = mem0 + S0;
    float* mem2 = mem1 + S0;

    const long ldx = (long)T_STEPS * 2048;

    const int n4_big = BATCH * 2048 / 4;   // 65536
    const int n_sm   = BATCH * 512;        // 65536

    for (int t = 0; t < T_STEPS; t++) {
        const long o0 = (long)t * BATCH * 2048;
        const long o2 = (long)t * BATCH * 512;

        // Layer 0
        gemm_partial_f32<<<dim3(64, 4), 256>>>(x + (long)t * 2048, ldx, W0, 2048, 2048);
        fold_lif_f32<<<n4_big / 256, 256>>>(
            th0, t ? (mem0 + o0 - (long)BATCH * 2048) : nullptr,
            mem0 + o0, spk0 + o0, n4_big);

        // Layer 1
        gemm_partial_f32<<<dim3(64, 4), 256>>>(spk0 + o0, 2048L, W1, 2048, 2048);
        fold_lif_f32<<<n4_big / 256, 256>>>(
            th1, t ? (mem1 + o0 - (long)BATCH * 2048) : nullptr,
            mem1 + o0, spk1 + o0, n4_big);

        // Layer 2 (fp64-exact)
        gemm_partial_f64<<<dim3(32, 4), 256>>>(spk1 + o0, W2, 2048, 512);
        fold_lif_f64<<<n_sm / 256, 256>>>(
            th2, t ? (mem2 + o2 - (long)BATCH * 512) : nullptr,
            mem2 + o2, spk2 + o2, n_sm);
    }
}